// round 13
// baseline (speedup 1.0000x reference)
#include <cuda_runtime.h>
#include <cuda_fp16.h>
#include <cstdint>
#include <cstddef>

// ============================================================================
// TurboQuantMSE via mma.sync fp16 (HMMA, sm_80 ISA — valid on plain sm_103).
// Both GEMMs are SINGLE-product fp16 (operands scaled by 2^10), 128x256
// tiles / 512 threads. GEMM1 flags boundary-adjacent values (THR=16 scaled
// units) into per-row buckets. Repair (row-bucketed, exact fp32) runs on a
// SIDE STREAM concurrently with GEMM2 (graph-captured fork/join via events):
// it patches idx and emits (r,c,delta) fixups; GEMM2 consumes UNREPAIRED
// yhat, and a final fixup kernel applies xhat[r,:] += delta*Pi[c,:] (exact).
// ============================================================================

#define DEVFN __device__ __forceinline__

namespace {
constexpr int N_  = 4096;
constexpr int D_  = 4096;
constexpr int BM  = 128;
constexpr int BN  = 256;
constexpr int BKE = 64;                 // K elements per chunk (fp16)
constexpr int NCH = D_ / BKE;           // 64 chunks
constexpr int NTH = 512;                // 16 warps

constexpr float SCALE   = 1024.0f;             // 2^10, exact
constexpr float YSCALE  = 1048576.0f;          // 2^20, exact
constexpr float INV_YS  = 1.0f / 1048576.0f;   // exact power of two
constexpr float THR     = 16.0f;               // flag threshold (scaled units)

constexpr int A_BYTES = BM * 128;       // 16 KB
constexpr int B_BYTES = BN * 128;       // 32 KB
constexpr int STAGE   = A_BYTES + B_BYTES;     // 48 KB
constexpr int NSTG    = 4;
constexpr int SMEM_SZ = NSTG * STAGE;          // 192 KB

constexpr int SLOTS = 96;               // flag slots per row (mean ~18, Poisson)
constexpr uint32_t FIX_CAP = 1u << 20;  // 1M fixup entries
}

// -------- device scratch (allocation-free rule: device globals) -------------
__device__ __half    g_xhi [(size_t)N_ * D_];
__device__ __half    g_phi [(size_t)D_ * D_];
__device__ __half    g_pthi[(size_t)D_ * D_];
__device__ __half    g_yhhi[(size_t)N_ * D_];
__device__ uint32_t  g_rowcnt[N_];
__device__ uint32_t  g_rowflag[(size_t)N_ * SLOTS];   // (c<<4)|q
__device__ uint32_t  g_fixi[FIX_CAP];                 // (r<<12)|c
__device__ float     g_fixd[FIX_CAP];                 // delta (unscaled)
__device__ uint32_t  g_fixcnt;

// ---------------------------- PTX helpers -----------------------------------
DEVFN uint32_t smem_u32(const void* p) {
    uint32_t a;
    asm("{ .reg .u64 t; cvta.to.shared.u64 t, %1; cvt.u32.u64 %0, t; }" : "=r"(a) : "l"(p));
    return a;
}
DEVFN void cpasync16(uint32_t s, const void* g) {
    asm volatile("cp.async.cg.shared.global [%0], [%1], 16;" :: "r"(s), "l"(g));
}
#define CP_COMMIT() asm volatile("cp.async.commit_group;" ::: "memory")
#define CP_WAIT2()  asm volatile("cp.async.wait_group 2;" ::: "memory")
#define CP_WAIT0()  asm volatile("cp.async.wait_group 0;" ::: "memory")

DEVFN void ldsm4(uint32_t* r, uint32_t addr) {
    asm volatile("ldmatrix.sync.aligned.m8n8.x4.shared.b16 {%0,%1,%2,%3}, [%4];"
                 : "=r"(r[0]), "=r"(r[1]), "=r"(r[2]), "=r"(r[3]) : "r"(addr));
}
DEVFN void mma16816(float* c, const uint32_t* a, const uint32_t* b) {
    asm volatile(
        "mma.sync.aligned.m16n8k16.row.col.f32.f16.f16.f32 "
        "{%0,%1,%2,%3}, {%4,%5,%6,%7}, {%8,%9}, {%0,%1,%2,%3};"
        : "+f"(c[0]), "+f"(c[1]), "+f"(c[2]), "+f"(c[3])
        : "r"(a[0]), "r"(a[1]), "r"(a[2]), "r"(a[3]), "r"(b[0]), "r"(b[1]));
}
DEVFN uint32_t pack2(__half a, __half b) {
    return (uint32_t)__half_as_ushort(a) | ((uint32_t)__half_as_ushort(b) << 16);
}
DEVFN uint32_t swz(uint32_t off) { return off ^ ((off >> 3) & 0x70); }

// ---------------------------- staging loader ---------------------------------
template<int ROWS>
DEVFN void ld_op(uint32_t sdst, const __half* __restrict__ g,
                 int row0, int kc, int tid)
{
    const char* gb = (const char*)g + ((size_t)row0 * D_ + (size_t)kc * BKE) * 2;
    constexpr int NOPS = ROWS * 8;             // 16B ops
#pragma unroll
    for (int i = 0; i < NOPS / NTH; ++i) {
        int idx = tid + i * NTH;
        int r = idx >> 3;
        int c = (idx & 7) << 4;
        cpasync16(sdst + swz((uint32_t)(r * 128 + c)),
                  gb + (size_t)r * (D_ * 2) + c);
    }
}

DEVFN void stage_load(uint32_t sb, int s, int kc,
                      const __half* A, const __half* B, int bm, int bn, int tid)
{
    const uint32_t st = sb + s * STAGE;
    ld_op<BM>(st,           A, bm, kc, tid);
    ld_op<BN>(st + A_BYTES, B, bn, kc, tid);
}

// ---------------------------- main GEMM kernel -------------------------------
// MODE 0: GEMM1 (x_hi, Pi_hi)     -> quantize epilogue, flag into row buckets
// MODE 1: GEMM2 (yhat_hi, PiT_hi) -> fp32 store * 2^-20
template<int MODE>
__global__ __launch_bounds__(NTH, 1)
void tq_mma(const float* __restrict__ cent, float* __restrict__ out0, int write_idx)
{
    extern __shared__ char smem[];
    const uint32_t sb = smem_u32(smem);
    const int tid = threadIdx.x, wid = tid >> 5, lid = tid & 31;
    const int bm = blockIdx.y * BM;
    const int bn = blockIdx.x * BN;

    const __half* A = (MODE == 0) ? g_xhi : g_yhhi;
    const __half* B = (MODE == 0) ? g_phi : g_pthi;

    __shared__ float    s_bound[16];
    __shared__ uint16_t s_chi[16];
    if (MODE == 0) {
        if (tid < 16) {
            float cs = cent[tid] * SCALE;           // exact
            s_chi[tid] = __half_as_ushort(__float2half_rn(cs));
        }
        if (tid < 15) s_bound[tid] = (0.5f * (cent[tid] + cent[tid + 1])) * YSCALE;
    }

    // 16 warps: 4 (M) x 4 (N), each 32x64
    const int wm = (wid & 3) * 32;
    const int wn = (wid >> 2) * 64;

    const int a_r = lid & 15;
    const int a_k = (lid >> 4) << 4;
    const int b_r = (lid & 7) | ((lid >> 4) << 3);
    const int b_k = ((lid >> 3) & 1) << 4;

    float acc[2][8][4];
#pragma unroll
    for (int i = 0; i < 2; ++i)
#pragma unroll
        for (int j = 0; j < 8; ++j)
#pragma unroll
            for (int k = 0; k < 4; ++k) acc[i][j][k] = 0.0f;

#pragma unroll
    for (int s = 0; s < 3; ++s) {
        stage_load(sb, s, s, A, B, bm, bn, tid);
        CP_COMMIT();
    }

    for (int t = 0; t < NCH; ++t) {
        if (t + 3 < NCH) CP_WAIT2(); else CP_WAIT0();
        __syncthreads();
        if (t + 3 < NCH) {
            stage_load(sb, (t + 3) & (NSTG - 1), t + 3, A, B, bm, bn, tid);
            CP_COMMIT();
        }
        const uint32_t st = sb + (t & (NSTG - 1)) * STAGE;
        const uint32_t pA = st;
        const uint32_t pB = st + A_BYTES;

        uint32_t a[2][4], b[4][4];
#pragma unroll
        for (int kk = 0; kk < 4; ++kk) {
#pragma unroll
            for (int mt = 0; mt < 2; ++mt)
                ldsm4(a[mt], pA + swz((uint32_t)((wm + mt * 16 + a_r) * 128 + kk * 32 + a_k)));
#pragma unroll
            for (int g = 0; g < 4; ++g)
                ldsm4(b[g], pB + swz((uint32_t)((wn + g * 16 + b_r) * 128 + kk * 32 + b_k)));
#pragma unroll
            for (int mt = 0; mt < 2; ++mt)
#pragma unroll
                for (int g = 0; g < 4; ++g) {
                    mma16816(acc[mt][2 * g],     a[mt], &b[g][0]);
                    mma16816(acc[mt][2 * g + 1], a[mt], &b[g][2]);
                }
        }
    }
    __syncthreads();

    // ------------------------------ epilogue ---------------------------------
    const int erow = (lid >> 2);
    const int ecol = (lid & 3) * 2;

    if (MODE == 1) {
#pragma unroll
        for (int mt = 0; mt < 2; ++mt) {
#pragma unroll
            for (int nt = 0; nt < 8; ++nt) {
                const int col = bn + wn + nt * 8 + ecol;
                const int r0  = bm + wm + mt * 16 + erow;
                float2 v0 = make_float2(acc[mt][nt][0] * INV_YS, acc[mt][nt][1] * INV_YS);
                float2 v1 = make_float2(acc[mt][nt][2] * INV_YS, acc[mt][nt][3] * INV_YS);
                *(float2*)(out0 + (size_t)r0 * D_ + col)       = v0;
                *(float2*)(out0 + (size_t)(r0 + 8) * D_ + col) = v1;
            }
        }
    } else {
        float bnd[15];
#pragma unroll
        for (int b0 = 0; b0 < 15; ++b0) bnd[b0] = s_bound[b0];
#pragma unroll
        for (int mt = 0; mt < 2; ++mt) {
#pragma unroll
            for (int nt = 0; nt < 8; ++nt) {
                const int col = bn + wn + nt * 8 + ecol;
#pragma unroll
                for (int half = 0; half < 2; ++half) {
                    const int r0 = bm + wm + mt * 16 + erow + half * 8;
                    float v0 = acc[mt][nt][half * 2 + 0];  // scaled y' = 2^20 y
                    float v1 = acc[mt][nt][half * 2 + 1];
                    int q0 = 0, q1 = 0;
#pragma unroll
                    for (int b0 = 0; b0 < 15; ++b0) {
                        q0 += (v0 > bnd[b0]) ? 1 : 0;
                        q1 += (v1 > bnd[b0]) ? 1 : 0;
                    }
                    float dl0 = (q0 > 0)  ? v0 - s_bound[q0 - 1] : 1e30f;
                    float dr0 = (q0 < 15) ? s_bound[q0] - v0     : 1e30f;
                    float dl1 = (q1 > 0)  ? v1 - s_bound[q1 - 1] : 1e30f;
                    float dr1 = (q1 < 15) ? s_bound[q1] - v1     : 1e30f;
                    if (fminf(dl0, dr0) < THR) {
                        uint32_t slot = atomicAdd(&g_rowcnt[r0], 1u);
                        if (slot < SLOTS)
                            g_rowflag[(size_t)r0 * SLOTS + slot] =
                                ((uint32_t)col << 4) | (uint32_t)q0;
                    }
                    if (fminf(dl1, dr1) < THR) {
                        uint32_t slot = atomicAdd(&g_rowcnt[r0], 1u);
                        if (slot < SLOTS)
                            g_rowflag[(size_t)r0 * SLOTS + slot] =
                                ((uint32_t)(col + 1) << 4) | (uint32_t)q1;
                    }
                    const size_t off = (size_t)r0 * D_ + col;
                    *(uint32_t*)(g_yhhi + off) =
                        (uint32_t)s_chi[q0] | ((uint32_t)s_chi[q1] << 16);
                    if (write_idx) {
                        float2 f = make_float2((float)q0, (float)q1);
                        *(float2*)(out0 + off) = f;
                    }
                }
            }
        }
    }
}

// ---------------------------- repair kernel -----------------------------------
// One CTA per row r: x[r,:] cached in smem; for each flagged (c, q_old), exact
// fp32 warp dot vs Pi[c,:] (L2-resident). Patches idx, emits (r,c,delta)
// fixups. Does NOT touch g_yhhi (GEMM2 is reading it concurrently).
__global__ __launch_bounds__(256)
void k_repair(const float* __restrict__ x, const float* __restrict__ Pi,
              const float* __restrict__ cent, float* __restrict__ idxf,
              int write_idx)
{
    __shared__ float xs[D_];
    const int r   = blockIdx.x;
    const int tid = threadIdx.x;
    const int wid = tid >> 5, lid = tid & 31;

    uint32_t cnt = g_rowcnt[r];
    if (cnt > SLOTS) cnt = SLOTS;
    if (cnt == 0) return;

    const float* xr = x + (size_t)r * D_;
#pragma unroll
    for (int i = 0; i < D_ / (256 * 4); ++i) {
        int k = (tid + i * 256) * 4;
        *(float4*)(xs + k) = *(const float4*)(xr + k);
    }
    __syncthreads();

    float c16[16], bnd[15];
#pragma unroll
    for (int i = 0; i < 16; ++i) c16[i] = __ldg(cent + i);
#pragma unroll
    for (int i = 0; i < 15; ++i) bnd[i] = 0.5f * (c16[i] + c16[i + 1]);

    for (uint32_t e = (uint32_t)wid; e < cnt; e += 8) {
        uint32_t item = g_rowflag[(size_t)r * SLOTS + e];
        int c    = (int)(item >> 4);
        int qold = (int)(item & 15u);
        const float* pr = Pi + (size_t)c * D_;
        float s0 = 0.f, s1 = 0.f, s2 = 0.f, s3 = 0.f;
#pragma unroll 4
        for (int k = lid * 4; k < D_; k += 128) {
            float4 a = *(const float4*)(xs + k);
            float4 b = *(const float4*)(pr + k);
            s0 = fmaf(a.x, b.x, s0); s1 = fmaf(a.y, b.y, s1);
            s2 = fmaf(a.z, b.z, s2); s3 = fmaf(a.w, b.w, s3);
        }
        float v = (s0 + s1) + (s2 + s3);
#pragma unroll
        for (int o = 16; o; o >>= 1) v += __shfl_xor_sync(0xFFFFFFFFu, v, o);
        if (lid == 0) {
            int q = 0;
#pragma unroll
            for (int b0 = 0; b0 < 15; ++b0) q += (v > bnd[b0]) ? 1 : 0;
            if (q != qold) {
                if (write_idx) idxf[(size_t)r * D_ + c] = (float)q;
                uint32_t fo = atomicAdd(&g_fixcnt, 1u);
                if (fo < FIX_CAP) {
                    g_fixi[fo] = ((uint32_t)r << 12) | (uint32_t)c;
                    g_fixd[fo] = c16[q] - c16[qold];
                }
            }
        }
    }
}

// ---------------------------- fixup kernel ------------------------------------
// xhat[r,:] += delta * Pi[c,:]  for each q-changed entry (rank-1, exact)
__global__ __launch_bounds__(256)
void k_fixup(const float* __restrict__ Pi, float* __restrict__ xhat)
{
    const int lid = threadIdx.x & 31;
    const int wg  = (blockIdx.x * blockDim.x + threadIdx.x) >> 5;
    const int nw  = (gridDim.x * blockDim.x) >> 5;

    uint32_t cnt = g_fixcnt;
    if (cnt > FIX_CAP) cnt = FIX_CAP;

    for (uint32_t e = (uint32_t)wg; e < cnt; e += (uint32_t)nw) {
        uint32_t item = g_fixi[e];
        int r = (int)(item >> 12);
        int c = (int)(item & 4095u);
        float d = g_fixd[e];
        const float* pr = Pi + (size_t)c * D_;
        float* xr = xhat + (size_t)r * D_;
#pragma unroll 2
        for (int k = lid * 4; k < D_; k += 128) {
            float4 p = *(const float4*)(pr + k);
            atomicAdd(xr + k + 0, d * p.x);
            atomicAdd(xr + k + 1, d * p.y);
            atomicAdd(xr + k + 2, d * p.z);
            atomicAdd(xr + k + 3, d * p.w);
        }
    }
}

// ---------------------------- prep kernels -----------------------------------
__global__ __launch_bounds__(256)
void k_cvt(const float* __restrict__ src, __half* __restrict__ hi)
{
    const uint32_t gtid = blockIdx.x * 256 + threadIdx.x;
    if (gtid < N_) g_rowcnt[gtid] = 0;
    if (gtid == 0) g_fixcnt = 0;
    const size_t i = (size_t)gtid * 4;
    float4 v = *(const float4*)(src + i);
    uint2 uh;
    uh.x = pack2(__float2half_rn(v.x * SCALE), __float2half_rn(v.y * SCALE));
    uh.y = pack2(__float2half_rn(v.z * SCALE), __float2half_rn(v.w * SCALE));
    *(uint2*)(hi + i) = uh;
}

// fused Pi prep: one read of Pi -> g_phi (row-major) + g_pthi (transposed)
__global__ __launch_bounds__(256)
void k_pi(const float* __restrict__ Pi)
{
    __shared__ __half tile[32][33];
    const int bx = blockIdx.x * 32, by = blockIdx.y * 32;
    const int tx = threadIdx.x & 31, ty = threadIdx.x >> 5;
#pragma unroll
    for (int r = 0; r < 4; ++r) {
        const int row = by + ty + r * 8;
        float v = Pi[(size_t)row * D_ + bx + tx] * SCALE;
        __half h = __float2half_rn(v);
        tile[ty + r * 8][tx] = h;
        g_phi[(size_t)row * D_ + bx + tx] = h;
    }
    __syncthreads();
#pragma unroll
    for (int r = 0; r < 4; ++r)
        g_pthi[(size_t)(bx + ty + r * 8) * D_ + by + tx] = tile[tx][ty + r * 8];
}

// ---------------------------- launch ------------------------------------------
extern "C" void kernel_launch(void* const* d_in, const int* in_sizes, int n_in,
                              void* d_out, int out_size)
{
    const float* x    = (const float*)d_in[0];
    const float* Pi   = (const float*)d_in[1];
    const float* cent = (const float*)d_in[2];

    float* out  = (float*)d_out;
    float* xhat = out;
    float* idxf = out + (size_t)N_ * D_;

    const long long total = (long long)N_ * D_;
    const int write_idx = ((long long)out_size >= 2 * total) ? 1 : 0;

    cudaFuncSetAttribute(tq_mma<0>, cudaFuncAttributeMaxDynamicSharedMemorySize, SMEM_SZ);
    cudaFuncSetAttribute(tq_mma<1>, cudaFuncAttributeMaxDynamicSharedMemorySize, SMEM_SZ);

    // side stream + fork/join events (host objects; created once, reused —
    // no device allocations, identical captured work on every call)
    static cudaStream_t s2 = nullptr;
    static cudaEvent_t  eFork = nullptr, eJoin = nullptr;
    if (s2 == nullptr) {
        cudaStreamCreateWithFlags(&s2, cudaStreamNonBlocking);
        cudaEventCreateWithFlags(&eFork, cudaEventDisableTiming);
        cudaEventCreateWithFlags(&eJoin, cudaEventDisableTiming);
    }

    __half* xhi_p;
    cudaGetSymbolAddress((void**)&xhi_p, g_xhi);

    const int nblk = (int)(total / (4 * 256));                 // 16384
    k_cvt<<<nblk, 256>>>(x, xhi_p);
    k_pi<<<dim3(D_ / 32, D_ / 32), 256>>>(Pi);

    dim3 grid(D_ / BN, N_ / BM);   // (16, 32)
    tq_mma<0><<<grid, NTH, SMEM_SZ>>>(cent, idxf, write_idx);

    // fork: repair on side stream, GEMM2 on main stream (concurrent)
    cudaEventRecord(eFork, 0);
    cudaStreamWaitEvent(s2, eFork, 0);
    k_repair<<<N_, 256, 0, s2>>>(x, Pi, cent, idxf, write_idx);
    tq_mma<1><<<grid, NTH, SMEM_SZ>>>(nullptr, xhat, 0);

    // join: fixup after both GEMM2 and repair complete
    cudaEventRecord(eJoin, s2);
    cudaStreamWaitEvent(0, eJoin, 0);
    k_fixup<<<256, 256>>>(Pi, xhat);
}

// round 14
// speedup vs baseline: 1.1947x; 1.1947x over previous
#include <cuda_runtime.h>
#include <cuda_fp16.h>
#include <cstdint>
#include <cstddef>

// ============================================================================
// TurboQuantMSE via mma.sync fp16 (HMMA, sm_80 ISA — valid on plain sm_103).
// Both GEMMs are SINGLE-product fp16 (operands scaled by 2^10), 128x256
// tiles / 512 threads (proven round-8/12 config).
// GEMM1 flags boundary-adjacent values (THR=14 scaled units, ~3.2 sigma of
// the calibrated fp16 operand-rounding residual sigma~4.35) into PER-ROW
// buckets; a repair kernel (one 512-thread CTA per row, x row in smem,
// Pi rows from L2) recomputes flagged dots exactly in fp32 and patches
// idx + yhat before GEMM2. All phases serialized (overlap falsified R10/11/13).
// ============================================================================

#define DEVFN __device__ __forceinline__

namespace {
constexpr int N_  = 4096;
constexpr int D_  = 4096;
constexpr int BM  = 128;
constexpr int BN  = 256;
constexpr int BKE = 64;                 // K elements per chunk (fp16)
constexpr int NCH = D_ / BKE;           // 64 chunks
constexpr int NTH = 512;                // 16 warps

constexpr float SCALE   = 1024.0f;             // 2^10, exact
constexpr float YSCALE  = 1048576.0f;          // 2^20, exact
constexpr float INV_YS  = 1.0f / 1048576.0f;   // exact power of two
constexpr float THR     = 14.0f;               // flag threshold (scaled units)

constexpr int A_BYTES = BM * 128;       // 16 KB
constexpr int B_BYTES = BN * 128;       // 32 KB
constexpr int STAGE   = A_BYTES + B_BYTES;     // 48 KB
constexpr int NSTG    = 4;
constexpr int SMEM_SZ = NSTG * STAGE;          // 192 KB

constexpr int SLOTS = 96;               // flag slots per row (mean ~16, Poisson)
constexpr int RTH   = 512;              // repair threads per CTA (16 warps)
}

// -------- device scratch (allocation-free rule: device globals) -------------
__device__ __half    g_xhi [(size_t)N_ * D_];
__device__ __half    g_phi [(size_t)D_ * D_];
__device__ __half    g_pthi[(size_t)D_ * D_];
__device__ __half    g_yhhi[(size_t)N_ * D_];
__device__ uint32_t  g_rowcnt[N_];
__device__ uint32_t  g_rowflag[(size_t)N_ * SLOTS];   // (c<<4)|q

// ---------------------------- PTX helpers -----------------------------------
DEVFN uint32_t smem_u32(const void* p) {
    uint32_t a;
    asm("{ .reg .u64 t; cvta.to.shared.u64 t, %1; cvt.u32.u64 %0, t; }" : "=r"(a) : "l"(p));
    return a;
}
DEVFN void cpasync16(uint32_t s, const void* g) {
    asm volatile("cp.async.cg.shared.global [%0], [%1], 16;" :: "r"(s), "l"(g));
}
#define CP_COMMIT() asm volatile("cp.async.commit_group;" ::: "memory")
#define CP_WAIT2()  asm volatile("cp.async.wait_group 2;" ::: "memory")
#define CP_WAIT0()  asm volatile("cp.async.wait_group 0;" ::: "memory")

DEVFN void ldsm4(uint32_t* r, uint32_t addr) {
    asm volatile("ldmatrix.sync.aligned.m8n8.x4.shared.b16 {%0,%1,%2,%3}, [%4];"
                 : "=r"(r[0]), "=r"(r[1]), "=r"(r[2]), "=r"(r[3]) : "r"(addr));
}
DEVFN void mma16816(float* c, const uint32_t* a, const uint32_t* b) {
    asm volatile(
        "mma.sync.aligned.m16n8k16.row.col.f32.f16.f16.f32 "
        "{%0,%1,%2,%3}, {%4,%5,%6,%7}, {%8,%9}, {%0,%1,%2,%3};"
        : "+f"(c[0]), "+f"(c[1]), "+f"(c[2]), "+f"(c[3])
        : "r"(a[0]), "r"(a[1]), "r"(a[2]), "r"(a[3]), "r"(b[0]), "r"(b[1]));
}
DEVFN uint32_t pack2(__half a, __half b) {
    return (uint32_t)__half_as_ushort(a) | ((uint32_t)__half_as_ushort(b) << 16);
}
DEVFN uint32_t swz(uint32_t off) { return off ^ ((off >> 3) & 0x70); }

// ---------------------------- staging loader ---------------------------------
template<int ROWS>
DEVFN void ld_op(uint32_t sdst, const __half* __restrict__ g,
                 int row0, int kc, int tid)
{
    const char* gb = (const char*)g + ((size_t)row0 * D_ + (size_t)kc * BKE) * 2;
    constexpr int NOPS = ROWS * 8;             // 16B ops
#pragma unroll
    for (int i = 0; i < NOPS / NTH; ++i) {
        int idx = tid + i * NTH;
        int r = idx >> 3;
        int c = (idx & 7) << 4;
        cpasync16(sdst + swz((uint32_t)(r * 128 + c)),
                  gb + (size_t)r * (D_ * 2) + c);
    }
}

DEVFN void stage_load(uint32_t sb, int s, int kc,
                      const __half* A, const __half* B, int bm, int bn, int tid)
{
    const uint32_t st = sb + s * STAGE;
    ld_op<BM>(st,           A, bm, kc, tid);
    ld_op<BN>(st + A_BYTES, B, bn, kc, tid);
}

// ---------------------------- main GEMM kernel -------------------------------
// MODE 0: GEMM1 (x_hi, Pi_hi)     -> quantize epilogue, flag into row buckets
// MODE 1: GEMM2 (yhat_hi, PiT_hi) -> fp32 store * 2^-20
template<int MODE>
__global__ __launch_bounds__(NTH, 1)
void tq_mma(const float* __restrict__ cent, float* __restrict__ out0, int write_idx)
{
    extern __shared__ char smem[];
    const uint32_t sb = smem_u32(smem);
    const int tid = threadIdx.x, wid = tid >> 5, lid = tid & 31;
    const int bm = blockIdx.y * BM;
    const int bn = blockIdx.x * BN;

    const __half* A = (MODE == 0) ? g_xhi : g_yhhi;
    const __half* B = (MODE == 0) ? g_phi : g_pthi;

    __shared__ float    s_bound[16];
    __shared__ uint16_t s_chi[16];
    if (MODE == 0) {
        if (tid < 16) {
            float cs = cent[tid] * SCALE;           // exact
            s_chi[tid] = __half_as_ushort(__float2half_rn(cs));
        }
        if (tid < 15) s_bound[tid] = (0.5f * (cent[tid] + cent[tid + 1])) * YSCALE;
    }

    // 16 warps: 4 (M) x 4 (N), each 32x64
    const int wm = (wid & 3) * 32;
    const int wn = (wid >> 2) * 64;

    const int a_r = lid & 15;
    const int a_k = (lid >> 4) << 4;
    const int b_r = (lid & 7) | ((lid >> 4) << 3);
    const int b_k = ((lid >> 3) & 1) << 4;

    float acc[2][8][4];
#pragma unroll
    for (int i = 0; i < 2; ++i)
#pragma unroll
        for (int j = 0; j < 8; ++j)
#pragma unroll
            for (int k = 0; k < 4; ++k) acc[i][j][k] = 0.0f;

#pragma unroll
    for (int s = 0; s < 3; ++s) {
        stage_load(sb, s, s, A, B, bm, bn, tid);
        CP_COMMIT();
    }

    for (int t = 0; t < NCH; ++t) {
        if (t + 3 < NCH) CP_WAIT2(); else CP_WAIT0();
        __syncthreads();
        if (t + 3 < NCH) {
            stage_load(sb, (t + 3) & (NSTG - 1), t + 3, A, B, bm, bn, tid);
            CP_COMMIT();
        }
        const uint32_t st = sb + (t & (NSTG - 1)) * STAGE;
        const uint32_t pA = st;
        const uint32_t pB = st + A_BYTES;

        uint32_t a[2][4], b[4][4];
#pragma unroll
        for (int kk = 0; kk < 4; ++kk) {
#pragma unroll
            for (int mt = 0; mt < 2; ++mt)
                ldsm4(a[mt], pA + swz((uint32_t)((wm + mt * 16 + a_r) * 128 + kk * 32 + a_k)));
#pragma unroll
            for (int g = 0; g < 4; ++g)
                ldsm4(b[g], pB + swz((uint32_t)((wn + g * 16 + b_r) * 128 + kk * 32 + b_k)));
#pragma unroll
            for (int mt = 0; mt < 2; ++mt)
#pragma unroll
                for (int g = 0; g < 4; ++g) {
                    mma16816(acc[mt][2 * g],     a[mt], &b[g][0]);
                    mma16816(acc[mt][2 * g + 1], a[mt], &b[g][2]);
                }
        }
    }
    __syncthreads();

    // ------------------------------ epilogue ---------------------------------
    const int erow = (lid >> 2);
    const int ecol = (lid & 3) * 2;

    if (MODE == 1) {
#pragma unroll
        for (int mt = 0; mt < 2; ++mt) {
#pragma unroll
            for (int nt = 0; nt < 8; ++nt) {
                const int col = bn + wn + nt * 8 + ecol;
                const int r0  = bm + wm + mt * 16 + erow;
                float2 v0 = make_float2(acc[mt][nt][0] * INV_YS, acc[mt][nt][1] * INV_YS);
                float2 v1 = make_float2(acc[mt][nt][2] * INV_YS, acc[mt][nt][3] * INV_YS);
                *(float2*)(out0 + (size_t)r0 * D_ + col)       = v0;
                *(float2*)(out0 + (size_t)(r0 + 8) * D_ + col) = v1;
            }
        }
    } else {
        float bnd[15];
#pragma unroll
        for (int b0 = 0; b0 < 15; ++b0) bnd[b0] = s_bound[b0];
#pragma unroll
        for (int mt = 0; mt < 2; ++mt) {
#pragma unroll
            for (int nt = 0; nt < 8; ++nt) {
                const int col = bn + wn + nt * 8 + ecol;
#pragma unroll
                for (int half = 0; half < 2; ++half) {
                    const int r0 = bm + wm + mt * 16 + erow + half * 8;
                    float v0 = acc[mt][nt][half * 2 + 0];  // scaled y' = 2^20 y
                    float v1 = acc[mt][nt][half * 2 + 1];
                    int q0 = 0, q1 = 0;
#pragma unroll
                    for (int b0 = 0; b0 < 15; ++b0) {
                        q0 += (v0 > bnd[b0]) ? 1 : 0;
                        q1 += (v1 > bnd[b0]) ? 1 : 0;
                    }
                    float dl0 = (q0 > 0)  ? v0 - s_bound[q0 - 1] : 1e30f;
                    float dr0 = (q0 < 15) ? s_bound[q0] - v0     : 1e30f;
                    float dl1 = (q1 > 0)  ? v1 - s_bound[q1 - 1] : 1e30f;
                    float dr1 = (q1 < 15) ? s_bound[q1] - v1     : 1e30f;
                    if (fminf(dl0, dr0) < THR) {
                        uint32_t slot = atomicAdd(&g_rowcnt[r0], 1u);
                        if (slot < SLOTS)
                            g_rowflag[(size_t)r0 * SLOTS + slot] =
                                ((uint32_t)col << 4) | (uint32_t)q0;
                    }
                    if (fminf(dl1, dr1) < THR) {
                        uint32_t slot = atomicAdd(&g_rowcnt[r0], 1u);
                        if (slot < SLOTS)
                            g_rowflag[(size_t)r0 * SLOTS + slot] =
                                ((uint32_t)(col + 1) << 4) | (uint32_t)q1;
                    }
                    const size_t off = (size_t)r0 * D_ + col;
                    *(uint32_t*)(g_yhhi + off) =
                        (uint32_t)s_chi[q0] | ((uint32_t)s_chi[q1] << 16);
                    if (write_idx) {
                        float2 f = make_float2((float)q0, (float)q1);
                        *(float2*)(out0 + off) = f;
                    }
                }
            }
        }
    }
}

// ---------------------------- repair kernel -----------------------------------
// One 512-thread CTA per row r: x[r,:] cached in smem; all flagged dots of the
// row run in parallel across 16 warps (exact fp32 vs Pi[c,:] from L2).
__global__ __launch_bounds__(RTH)
void k_repair(const float* __restrict__ x, const float* __restrict__ Pi,
              const float* __restrict__ cent, float* __restrict__ idxf,
              int write_idx)
{
    __shared__ float xs[D_];
    const int r   = blockIdx.x;
    const int tid = threadIdx.x;
    const int wid = tid >> 5, lid = tid & 31;

    uint32_t cnt = g_rowcnt[r];
    if (cnt > SLOTS) cnt = SLOTS;
    if (cnt == 0) return;

    const float* xr = x + (size_t)r * D_;
#pragma unroll
    for (int i = 0; i < D_ / (RTH * 4); ++i) {
        int k = (tid + i * RTH) * 4;
        *(float4*)(xs + k) = *(const float4*)(xr + k);
    }
    __syncthreads();

    float c16[16], bnd[15];
#pragma unroll
    for (int i = 0; i < 16; ++i) c16[i] = __ldg(cent + i);
#pragma unroll
    for (int i = 0; i < 15; ++i) bnd[i] = 0.5f * (c16[i] + c16[i + 1]);

    for (uint32_t e = (uint32_t)wid; e < cnt; e += (RTH / 32)) {
        uint32_t item = g_rowflag[(size_t)r * SLOTS + e];
        int c    = (int)(item >> 4);
        int qold = (int)(item & 15u);
        const float* pr = Pi + (size_t)c * D_;
        float s0 = 0.f, s1 = 0.f, s2 = 0.f, s3 = 0.f;
#pragma unroll 4
        for (int k = lid * 4; k < D_; k += 128) {
            float4 a = *(const float4*)(xs + k);
            float4 b = *(const float4*)(pr + k);
            s0 = fmaf(a.x, b.x, s0); s1 = fmaf(a.y, b.y, s1);
            s2 = fmaf(a.z, b.z, s2); s3 = fmaf(a.w, b.w, s3);
        }
        float v = (s0 + s1) + (s2 + s3);
#pragma unroll
        for (int o = 16; o; o >>= 1) v += __shfl_xor_sync(0xFFFFFFFFu, v, o);
        if (lid == 0) {
            int q = 0;
#pragma unroll
            for (int b0 = 0; b0 < 15; ++b0) q += (v > bnd[b0]) ? 1 : 0;
            if (q != qold) {
                const size_t off = (size_t)r * D_ + c;
                g_yhhi[off] = __float2half_rn(c16[q] * SCALE);
                if (write_idx) idxf[off] = (float)q;
            }
        }
    }
}

// ---------------------------- prep kernels -----------------------------------
__global__ __launch_bounds__(256)
void k_cvt(const float* __restrict__ src, __half* __restrict__ hi)
{
    const uint32_t gtid = blockIdx.x * 256 + threadIdx.x;
    if (gtid < N_) g_rowcnt[gtid] = 0;
    const size_t i = (size_t)gtid * 4;
    float4 v = *(const float4*)(src + i);
    uint2 uh;
    uh.x = pack2(__float2half_rn(v.x * SCALE), __float2half_rn(v.y * SCALE));
    uh.y = pack2(__float2half_rn(v.z * SCALE), __float2half_rn(v.w * SCALE));
    *(uint2*)(hi + i) = uh;
}

// fused Pi prep: one read of Pi -> g_phi (row-major) + g_pthi (transposed)
__global__ __launch_bounds__(256)
void k_pi(const float* __restrict__ Pi)
{
    __shared__ __half tile[32][33];
    const int bx = blockIdx.x * 32, by = blockIdx.y * 32;
    const int tx = threadIdx.x & 31, ty = threadIdx.x >> 5;
#pragma unroll
    for (int r = 0; r < 4; ++r) {
        const int row = by + ty + r * 8;
        float v = Pi[(size_t)row * D_ + bx + tx] * SCALE;
        __half h = __float2half_rn(v);
        tile[ty + r * 8][tx] = h;
        g_phi[(size_t)row * D_ + bx + tx] = h;
    }
    __syncthreads();
#pragma unroll
    for (int r = 0; r < 4; ++r)
        g_pthi[(size_t)(bx + ty + r * 8) * D_ + by + tx] = tile[tx][ty + r * 8];
}

// ---------------------------- launch ------------------------------------------
extern "C" void kernel_launch(void* const* d_in, const int* in_sizes, int n_in,
                              void* d_out, int out_size)
{
    const float* x    = (const float*)d_in[0];
    const float* Pi   = (const float*)d_in[1];
    const float* cent = (const float*)d_in[2];

    float* out  = (float*)d_out;
    float* xhat = out;
    float* idxf = out + (size_t)N_ * D_;

    const long long total = (long long)N_ * D_;
    const int write_idx = ((long long)out_size >= 2 * total) ? 1 : 0;

    cudaFuncSetAttribute(tq_mma<0>, cudaFuncAttributeMaxDynamicSharedMemorySize, SMEM_SZ);
    cudaFuncSetAttribute(tq_mma<1>, cudaFuncAttributeMaxDynamicSharedMemorySize, SMEM_SZ);

    __half* xhi_p;
    cudaGetSymbolAddress((void**)&xhi_p, g_xhi);

    const int nblk = (int)(total / (4 * 256));                 // 16384
    k_cvt<<<nblk, 256>>>(x, xhi_p);
    k_pi<<<dim3(D_ / 32, D_ / 32), 256>>>(Pi);

    dim3 grid(D_ / BN, N_ / BM);   // (16, 32)
    tq_mma<0><<<grid, NTH, SMEM_SZ>>>(cent, idxf, write_idx);
    k_repair<<<N_, RTH>>>(x, Pi, cent, idxf, write_idx);
    tq_mma<1><<<grid, NTH, SMEM_SZ>>>(nullptr, xhat, 0);
}

// round 15
// speedup vs baseline: 1.3212x; 1.1059x over previous
#include <cuda_runtime.h>
#include <cuda_fp16.h>
#include <cstdint>
#include <cstddef>

// ============================================================================
// TurboQuantMSE via mma.sync fp16 (HMMA, sm_80 ISA — valid on plain sm_103).
// Both GEMMs are SINGLE-product fp16 (operands scaled by 2^10).
// NEW: 128x128 tiles, 256 threads, 2 CTAs/SM (launch_bounds(256,2), 3-stage
// 96KB pipeline) — keeps 16 warps/SM while killing wave quantization
// (1024 CTAs, 2-deep occupancy smooths the tail; round-9's 1-CTA/SM version
// lost latency hiding, this one doesn't).
// GEMM1 flags boundary-adjacent values (THR=16 scaled units) into PER-ROW
// buckets; repair (one 256-thread CTA per row, x row in smem, Pi from L2)
// recomputes flagged dots exactly in fp32 and patches idx + yhat before GEMM2.
// ============================================================================

#define DEVFN __device__ __forceinline__

namespace {
constexpr int N_  = 4096;
constexpr int D_  = 4096;
constexpr int BM  = 128;
constexpr int BN  = 128;
constexpr int BKE = 64;                 // K elements per chunk (fp16)
constexpr int NCH = D_ / BKE;           // 64 chunks
constexpr int NTH = 256;                // 8 warps, 2 CTAs/SM

constexpr float SCALE   = 1024.0f;             // 2^10, exact
constexpr float YSCALE  = 1048576.0f;          // 2^20, exact
constexpr float INV_YS  = 1.0f / 1048576.0f;   // exact power of two
constexpr float THR     = 16.0f;               // flag threshold (scaled units)

constexpr int A_BYTES = BM * 128;       // 16 KB
constexpr int B_BYTES = BN * 128;       // 16 KB
constexpr int STAGE   = A_BYTES + B_BYTES;     // 32 KB
constexpr int NSTG    = 3;
constexpr int SMEM_SZ = NSTG * STAGE;          // 96 KB

constexpr int SLOTS = 96;               // flag slots per row (mean ~18)
}

// -------- device scratch (allocation-free rule: device globals) -------------
__device__ __half    g_xhi [(size_t)N_ * D_];
__device__ __half    g_phi [(size_t)D_ * D_];
__device__ __half    g_pthi[(size_t)D_ * D_];
__device__ __half    g_yhhi[(size_t)N_ * D_];
__device__ uint32_t  g_rowcnt[N_];
__device__ uint32_t  g_rowflag[(size_t)N_ * SLOTS];   // (c<<4)|q

// ---------------------------- PTX helpers -----------------------------------
DEVFN uint32_t smem_u32(const void* p) {
    uint32_t a;
    asm("{ .reg .u64 t; cvta.to.shared.u64 t, %1; cvt.u32.u64 %0, t; }" : "=r"(a) : "l"(p));
    return a;
}
DEVFN void cpasync16(uint32_t s, const void* g) {
    asm volatile("cp.async.cg.shared.global [%0], [%1], 16;" :: "r"(s), "l"(g));
}
#define CP_COMMIT() asm volatile("cp.async.commit_group;" ::: "memory")
#define CP_WAIT1()  asm volatile("cp.async.wait_group 1;" ::: "memory")
#define CP_WAIT0()  asm volatile("cp.async.wait_group 0;" ::: "memory")

DEVFN void ldsm4(uint32_t* r, uint32_t addr) {
    asm volatile("ldmatrix.sync.aligned.m8n8.x4.shared.b16 {%0,%1,%2,%3}, [%4];"
                 : "=r"(r[0]), "=r"(r[1]), "=r"(r[2]), "=r"(r[3]) : "r"(addr));
}
DEVFN void mma16816(float* c, const uint32_t* a, const uint32_t* b) {
    asm volatile(
        "mma.sync.aligned.m16n8k16.row.col.f32.f16.f16.f32 "
        "{%0,%1,%2,%3}, {%4,%5,%6,%7}, {%8,%9}, {%0,%1,%2,%3};"
        : "+f"(c[0]), "+f"(c[1]), "+f"(c[2]), "+f"(c[3])
        : "r"(a[0]), "r"(a[1]), "r"(a[2]), "r"(a[3]), "r"(b[0]), "r"(b[1]));
}
DEVFN uint32_t pack2(__half a, __half b) {
    return (uint32_t)__half_as_ushort(a) | ((uint32_t)__half_as_ushort(b) << 16);
}
DEVFN uint32_t swz(uint32_t off) { return off ^ ((off >> 3) & 0x70); }

// ---------------------------- staging loader ---------------------------------
template<int ROWS>
DEVFN void ld_op(uint32_t sdst, const __half* __restrict__ g,
                 int row0, int kc, int tid)
{
    const char* gb = (const char*)g + ((size_t)row0 * D_ + (size_t)kc * BKE) * 2;
    constexpr int NOPS = ROWS * 8;             // 16B ops
#pragma unroll
    for (int i = 0; i < NOPS / NTH; ++i) {
        int idx = tid + i * NTH;
        int r = idx >> 3;
        int c = (idx & 7) << 4;
        cpasync16(sdst + swz((uint32_t)(r * 128 + c)),
                  gb + (size_t)r * (D_ * 2) + c);
    }
}

DEVFN void stage_load(uint32_t sb, int s, int kc,
                      const __half* A, const __half* B, int bm, int bn, int tid)
{
    const uint32_t st = sb + s * STAGE;
    ld_op<BM>(st,           A, bm, kc, tid);
    ld_op<BN>(st + A_BYTES, B, bn, kc, tid);
}

// ---------------------------- main GEMM kernel -------------------------------
// MODE 0: GEMM1 (x_hi, Pi_hi)     -> quantize epilogue, flag into row buckets
// MODE 1: GEMM2 (yhat_hi, PiT_hi) -> fp32 store * 2^-20
template<int MODE>
__global__ __launch_bounds__(NTH, 2)
void tq_mma(const float* __restrict__ cent, float* __restrict__ out0, int write_idx)
{
    extern __shared__ char smem[];
    const uint32_t sb = smem_u32(smem);
    const int tid = threadIdx.x, wid = tid >> 5, lid = tid & 31;
    const int bm = blockIdx.y * BM;
    const int bn = blockIdx.x * BN;

    const __half* A = (MODE == 0) ? g_xhi : g_yhhi;
    const __half* B = (MODE == 0) ? g_phi : g_pthi;

    __shared__ float    s_bound[16];
    __shared__ uint16_t s_chi[16];
    if (MODE == 0) {
        if (tid < 16) {
            float cs = cent[tid] * SCALE;           // exact
            s_chi[tid] = __half_as_ushort(__float2half_rn(cs));
        }
        if (tid < 15) s_bound[tid] = (0.5f * (cent[tid] + cent[tid + 1])) * YSCALE;
    }

    // 8 warps: 4 (M) x 2 (N), each 32x64
    const int wm = (wid & 3) * 32;
    const int wn = (wid >> 2) * 64;

    const int a_r = lid & 15;
    const int a_k = (lid >> 4) << 4;
    const int b_r = (lid & 7) | ((lid >> 4) << 3);
    const int b_k = ((lid >> 3) & 1) << 4;

    float acc[2][8][4];
#pragma unroll
    for (int i = 0; i < 2; ++i)
#pragma unroll
        for (int j = 0; j < 8; ++j)
#pragma unroll
            for (int k = 0; k < 4; ++k) acc[i][j][k] = 0.0f;

    // prologue: prime 2 of 3 stages
#pragma unroll
    for (int s = 0; s < 2; ++s) {
        stage_load(sb, s, s, A, B, bm, bn, tid);
        CP_COMMIT();
    }

    for (int t = 0; t < NCH; ++t) {
        if (t + 2 < NCH) CP_WAIT1(); else CP_WAIT0();
        __syncthreads();
        if (t + 2 < NCH) {
            stage_load(sb, (t + 2) % NSTG, t + 2, A, B, bm, bn, tid);
            CP_COMMIT();
        }
        const uint32_t st = sb + (t % NSTG) * STAGE;
        const uint32_t pA = st;
        const uint32_t pB = st + A_BYTES;

        uint32_t a[2][4], b[4][4];
#pragma unroll
        for (int kk = 0; kk < 4; ++kk) {
#pragma unroll
            for (int mt = 0; mt < 2; ++mt)
                ldsm4(a[mt], pA + swz((uint32_t)((wm + mt * 16 + a_r) * 128 + kk * 32 + a_k)));
#pragma unroll
            for (int g = 0; g < 4; ++g)
                ldsm4(b[g], pB + swz((uint32_t)((wn + g * 16 + b_r) * 128 + kk * 32 + b_k)));
#pragma unroll
            for (int mt = 0; mt < 2; ++mt)
#pragma unroll
                for (int g = 0; g < 4; ++g) {
                    mma16816(acc[mt][2 * g],     a[mt], &b[g][0]);
                    mma16816(acc[mt][2 * g + 1], a[mt], &b[g][2]);
                }
        }
        __syncthreads();
    }

    // ------------------------------ epilogue ---------------------------------
    const int erow = (lid >> 2);
    const int ecol = (lid & 3) * 2;

    if (MODE == 1) {
#pragma unroll
        for (int mt = 0; mt < 2; ++mt) {
#pragma unroll
            for (int nt = 0; nt < 8; ++nt) {
                const int col = bn + wn + nt * 8 + ecol;
                const int r0  = bm + wm + mt * 16 + erow;
                float2 v0 = make_float2(acc[mt][nt][0] * INV_YS, acc[mt][nt][1] * INV_YS);
                float2 v1 = make_float2(acc[mt][nt][2] * INV_YS, acc[mt][nt][3] * INV_YS);
                *(float2*)(out0 + (size_t)r0 * D_ + col)       = v0;
                *(float2*)(out0 + (size_t)(r0 + 8) * D_ + col) = v1;
            }
        }
    } else {
        float bnd[15];
#pragma unroll
        for (int b0 = 0; b0 < 15; ++b0) bnd[b0] = s_bound[b0];
#pragma unroll
        for (int mt = 0; mt < 2; ++mt) {
#pragma unroll
            for (int nt = 0; nt < 8; ++nt) {
                const int col = bn + wn + nt * 8 + ecol;
#pragma unroll
                for (int half = 0; half < 2; ++half) {
                    const int r0 = bm + wm + mt * 16 + erow + half * 8;
                    float v0 = acc[mt][nt][half * 2 + 0];  // scaled y' = 2^20 y
                    float v1 = acc[mt][nt][half * 2 + 1];
                    int q0 = 0, q1 = 0;
#pragma unroll
                    for (int b0 = 0; b0 < 15; ++b0) {
                        q0 += (v0 > bnd[b0]) ? 1 : 0;
                        q1 += (v1 > bnd[b0]) ? 1 : 0;
                    }
                    float dl0 = (q0 > 0)  ? v0 - s_bound[q0 - 1] : 1e30f;
                    float dr0 = (q0 < 15) ? s_bound[q0] - v0     : 1e30f;
                    float dl1 = (q1 > 0)  ? v1 - s_bound[q1 - 1] : 1e30f;
                    float dr1 = (q1 < 15) ? s_bound[q1] - v1     : 1e30f;
                    if (fminf(dl0, dr0) < THR) {
                        uint32_t slot = atomicAdd(&g_rowcnt[r0], 1u);
                        if (slot < SLOTS)
                            g_rowflag[(size_t)r0 * SLOTS + slot] =
                                ((uint32_t)col << 4) | (uint32_t)q0;
                    }
                    if (fminf(dl1, dr1) < THR) {
                        uint32_t slot = atomicAdd(&g_rowcnt[r0], 1u);
                        if (slot < SLOTS)
                            g_rowflag[(size_t)r0 * SLOTS + slot] =
                                ((uint32_t)(col + 1) << 4) | (uint32_t)q1;
                    }
                    const size_t off = (size_t)r0 * D_ + col;
                    *(uint32_t*)(g_yhhi + off) =
                        (uint32_t)s_chi[q0] | ((uint32_t)s_chi[q1] << 16);
                    if (write_idx) {
                        float2 f = make_float2((float)q0, (float)q1);
                        *(float2*)(out0 + off) = f;
                    }
                }
            }
        }
    }
}

// ---------------------------- repair kernel -----------------------------------
// One 256-thread CTA per row r: x[r,:] cached in smem; for each flagged
// (c, q_old), exact fp32 warp dot vs Pi[c,:] (L2-resident), patch yhat + idx.
__global__ __launch_bounds__(256)
void k_repair(const float* __restrict__ x, const float* __restrict__ Pi,
              const float* __restrict__ cent, float* __restrict__ idxf,
              int write_idx)
{
    __shared__ float xs[D_];
    const int r   = blockIdx.x;
    const int tid = threadIdx.x;
    const int wid = tid >> 5, lid = tid & 31;

    uint32_t cnt = g_rowcnt[r];
    if (cnt > SLOTS) cnt = SLOTS;
    if (cnt == 0) return;

    const float* xr = x + (size_t)r * D_;
#pragma unroll
    for (int i = 0; i < D_ / (256 * 4); ++i) {
        int k = (tid + i * 256) * 4;
        *(float4*)(xs + k) = *(const float4*)(xr + k);
    }
    __syncthreads();

    float c16[16], bnd[15];
#pragma unroll
    for (int i = 0; i < 16; ++i) c16[i] = __ldg(cent + i);
#pragma unroll
    for (int i = 0; i < 15; ++i) bnd[i] = 0.5f * (c16[i] + c16[i + 1]);

    for (uint32_t e = (uint32_t)wid; e < cnt; e += 8) {
        uint32_t item = g_rowflag[(size_t)r * SLOTS + e];
        int c    = (int)(item >> 4);
        int qold = (int)(item & 15u);
        const float* pr = Pi + (size_t)c * D_;
        float s0 = 0.f, s1 = 0.f, s2 = 0.f, s3 = 0.f;
#pragma unroll 4
        for (int k = lid * 4; k < D_; k += 128) {
            float4 a = *(const float4*)(xs + k);
            float4 b = *(const float4*)(pr + k);
            s0 = fmaf(a.x, b.x, s0); s1 = fmaf(a.y, b.y, s1);
            s2 = fmaf(a.z, b.z, s2); s3 = fmaf(a.w, b.w, s3);
        }
        float v = (s0 + s1) + (s2 + s3);
#pragma unroll
        for (int o = 16; o; o >>= 1) v += __shfl_xor_sync(0xFFFFFFFFu, v, o);
        if (lid == 0) {
            int q = 0;
#pragma unroll
            for (int b0 = 0; b0 < 15; ++b0) q += (v > bnd[b0]) ? 1 : 0;
            if (q != qold) {
                const size_t off = (size_t)r * D_ + c;
                g_yhhi[off] = __float2half_rn(c16[q] * SCALE);
                if (write_idx) idxf[off] = (float)q;
            }
        }
    }
}

// ---------------------------- prep kernels -----------------------------------
__global__ __launch_bounds__(256)
void k_cvt(const float* __restrict__ src, __half* __restrict__ hi)
{
    const uint32_t gtid = blockIdx.x * 256 + threadIdx.x;
    if (gtid < N_) g_rowcnt[gtid] = 0;
    const size_t i = (size_t)gtid * 4;
    float4 v = *(const float4*)(src + i);
    uint2 uh;
    uh.x = pack2(__float2half_rn(v.x * SCALE), __float2half_rn(v.y * SCALE));
    uh.y = pack2(__float2half_rn(v.z * SCALE), __float2half_rn(v.w * SCALE));
    *(uint2*)(hi + i) = uh;
}

// fused Pi prep: one read of Pi -> g_phi (row-major) + g_pthi (transposed)
__global__ __launch_bounds__(256)
void k_pi(const float* __restrict__ Pi)
{
    __shared__ __half tile[32][33];
    const int bx = blockIdx.x * 32, by = blockIdx.y * 32;
    const int tx = threadIdx.x & 31, ty = threadIdx.x >> 5;
#pragma unroll
    for (int r = 0; r < 4; ++r) {
        const int row = by + ty + r * 8;
        float v = Pi[(size_t)row * D_ + bx + tx] * SCALE;
        __half h = __float2half_rn(v);
        tile[ty + r * 8][tx] = h;
        g_phi[(size_t)row * D_ + bx + tx] = h;
    }
    __syncthreads();
#pragma unroll
    for (int r = 0; r < 4; ++r)
        g_pthi[(size_t)(bx + ty + r * 8) * D_ + by + tx] = tile[tx][ty + r * 8];
}

// ---------------------------- launch ------------------------------------------
extern "C" void kernel_launch(void* const* d_in, const int* in_sizes, int n_in,
                              void* d_out, int out_size)
{
    const float* x    = (const float*)d_in[0];
    const float* Pi   = (const float*)d_in[1];
    const float* cent = (const float*)d_in[2];

    float* out  = (float*)d_out;
    float* xhat = out;
    float* idxf = out + (size_t)N_ * D_;

    const long long total = (long long)N_ * D_;
    const int write_idx = ((long long)out_size >= 2 * total) ? 1 : 0;

    cudaFuncSetAttribute(tq_mma<0>, cudaFuncAttributeMaxDynamicSharedMemorySize, SMEM_SZ);
    cudaFuncSetAttribute(tq_mma<1>, cudaFuncAttributeMaxDynamicSharedMemorySize, SMEM_SZ);

    __half* xhi_p;
    cudaGetSymbolAddress((void**)&xhi_p, g_xhi);

    const int nblk = (int)(total / (4 * 256));                 // 16384
    k_cvt<<<nblk, 256>>>(x, xhi_p);
    k_pi<<<dim3(D_ / 32, D_ / 32), 256>>>(Pi);

    dim3 grid(D_ / BN, N_ / BM);   // (32, 32) = 1024 CTAs, 2 per SM
    tq_mma<0><<<grid, NTH, SMEM_SZ>>>(cent, idxf, write_idx);
    k_repair<<<N_, 256>>>(x, Pi, cent, idxf, write_idx);
    tq_mma<1><<<grid, NTH, SMEM_SZ>>>(nullptr, xhat, 0);
}

// round 16
// speedup vs baseline: 1.3421x; 1.0158x over previous
#include <cuda_runtime.h>
#include <cuda_fp16.h>
#include <cstdint>
#include <cstddef>

// ============================================================================
// TurboQuantMSE via mma.sync fp16 (HMMA, sm_80 ISA — valid on plain sm_103).
// Both GEMMs are SINGLE-product fp16 (operands scaled by 2^10).
// 128x128 tiles, 256 threads, 2 CTAs/SM (launch_bounds(256,2), 3-stage 96KB
// pipeline) — 16 warps/SM with smoothed wave tails (round-15 winner).
// GEMM1 flags boundary-adjacent values (THR=14 scaled units, 3.2 sigma of
// calibrated residual sigma=4.35; rel_err 5.63e-4 measured round 14) into
// PER-ROW buckets; repair (one 256-thread CTA per row, x row in smem, Pi
// from L2, unroll-8 dot for MLP=16) patches idx + yhat before GEMM2.
// ============================================================================

#define DEVFN __device__ __forceinline__

namespace {
constexpr int N_  = 4096;
constexpr int D_  = 4096;
constexpr int BM  = 128;
constexpr int BN  = 128;
constexpr int BKE = 64;                 // K elements per chunk (fp16)
constexpr int NCH = D_ / BKE;           // 64 chunks
constexpr int NTH = 256;                // 8 warps, 2 CTAs/SM

constexpr float SCALE   = 1024.0f;             // 2^10, exact
constexpr float YSCALE  = 1048576.0f;          // 2^20, exact
constexpr float INV_YS  = 1.0f / 1048576.0f;   // exact power of two
constexpr float THR     = 14.0f;               // flag threshold (scaled units)

constexpr int A_BYTES = BM * 128;       // 16 KB
constexpr int B_BYTES = BN * 128;       // 16 KB
constexpr int STAGE   = A_BYTES + B_BYTES;     // 32 KB
constexpr int NSTG    = 3;
constexpr int SMEM_SZ = NSTG * STAGE;          // 96 KB

constexpr int SLOTS = 96;               // flag slots per row (mean ~16)
}

// -------- device scratch (allocation-free rule: device globals) -------------
__device__ __half    g_xhi [(size_t)N_ * D_];
__device__ __half    g_phi [(size_t)D_ * D_];
__device__ __half    g_pthi[(size_t)D_ * D_];
__device__ __half    g_yhhi[(size_t)N_ * D_];
__device__ uint32_t  g_rowcnt[N_];
__device__ uint32_t  g_rowflag[(size_t)N_ * SLOTS];   // (c<<4)|q

// ---------------------------- PTX helpers -----------------------------------
DEVFN uint32_t smem_u32(const void* p) {
    uint32_t a;
    asm("{ .reg .u64 t; cvta.to.shared.u64 t, %1; cvt.u32.u64 %0, t; }" : "=r"(a) : "l"(p));
    return a;
}
DEVFN void cpasync16(uint32_t s, const void* g) {
    asm volatile("cp.async.cg.shared.global [%0], [%1], 16;" :: "r"(s), "l"(g));
}
#define CP_COMMIT() asm volatile("cp.async.commit_group;" ::: "memory")
#define CP_WAIT1()  asm volatile("cp.async.wait_group 1;" ::: "memory")
#define CP_WAIT0()  asm volatile("cp.async.wait_group 0;" ::: "memory")

DEVFN void ldsm4(uint32_t* r, uint32_t addr) {
    asm volatile("ldmatrix.sync.aligned.m8n8.x4.shared.b16 {%0,%1,%2,%3}, [%4];"
                 : "=r"(r[0]), "=r"(r[1]), "=r"(r[2]), "=r"(r[3]) : "r"(addr));
}
DEVFN void mma16816(float* c, const uint32_t* a, const uint32_t* b) {
    asm volatile(
        "mma.sync.aligned.m16n8k16.row.col.f32.f16.f16.f32 "
        "{%0,%1,%2,%3}, {%4,%5,%6,%7}, {%8,%9}, {%0,%1,%2,%3};"
        : "+f"(c[0]), "+f"(c[1]), "+f"(c[2]), "+f"(c[3])
        : "r"(a[0]), "r"(a[1]), "r"(a[2]), "r"(a[3]), "r"(b[0]), "r"(b[1]));
}
DEVFN uint32_t pack2(__half a, __half b) {
    return (uint32_t)__half_as_ushort(a) | ((uint32_t)__half_as_ushort(b) << 16);
}
DEVFN uint32_t swz(uint32_t off) { return off ^ ((off >> 3) & 0x70); }

// ---------------------------- staging loader ---------------------------------
template<int ROWS>
DEVFN void ld_op(uint32_t sdst, const __half* __restrict__ g,
                 int row0, int kc, int tid)
{
    const char* gb = (const char*)g + ((size_t)row0 * D_ + (size_t)kc * BKE) * 2;
    constexpr int NOPS = ROWS * 8;             // 16B ops
#pragma unroll
    for (int i = 0; i < NOPS / NTH; ++i) {
        int idx = tid + i * NTH;
        int r = idx >> 3;
        int c = (idx & 7) << 4;
        cpasync16(sdst + swz((uint32_t)(r * 128 + c)),
                  gb + (size_t)r * (D_ * 2) + c);
    }
}

DEVFN void stage_load(uint32_t sb, int s, int kc,
                      const __half* A, const __half* B, int bm, int bn, int tid)
{
    const uint32_t st = sb + s * STAGE;
    ld_op<BM>(st,           A, bm, kc, tid);
    ld_op<BN>(st + A_BYTES, B, bn, kc, tid);
}

// ---------------------------- main GEMM kernel -------------------------------
// MODE 0: GEMM1 (x_hi, Pi_hi)     -> quantize epilogue, flag into row buckets
// MODE 1: GEMM2 (yhat_hi, PiT_hi) -> fp32 store * 2^-20
template<int MODE>
__global__ __launch_bounds__(NTH, 2)
void tq_mma(const float* __restrict__ cent, float* __restrict__ out0, int write_idx)
{
    extern __shared__ char smem[];
    const uint32_t sb = smem_u32(smem);
    const int tid = threadIdx.x, wid = tid >> 5, lid = tid & 31;
    const int bm = blockIdx.y * BM;
    const int bn = blockIdx.x * BN;

    const __half* A = (MODE == 0) ? g_xhi : g_yhhi;
    const __half* B = (MODE == 0) ? g_phi : g_pthi;

    __shared__ float    s_bound[16];
    __shared__ uint16_t s_chi[16];
    if (MODE == 0) {
        if (tid < 16) {
            float cs = cent[tid] * SCALE;           // exact
            s_chi[tid] = __half_as_ushort(__float2half_rn(cs));
        }
        if (tid < 15) s_bound[tid] = (0.5f * (cent[tid] + cent[tid + 1])) * YSCALE;
    }

    // 8 warps: 4 (M) x 2 (N), each 32x64
    const int wm = (wid & 3) * 32;
    const int wn = (wid >> 2) * 64;

    const int a_r = lid & 15;
    const int a_k = (lid >> 4) << 4;
    const int b_r = (lid & 7) | ((lid >> 4) << 3);
    const int b_k = ((lid >> 3) & 1) << 4;

    float acc[2][8][4];
#pragma unroll
    for (int i = 0; i < 2; ++i)
#pragma unroll
        for (int j = 0; j < 8; ++j)
#pragma unroll
            for (int k = 0; k < 4; ++k) acc[i][j][k] = 0.0f;

    // prologue: prime 2 of 3 stages
#pragma unroll
    for (int s = 0; s < 2; ++s) {
        stage_load(sb, s, s, A, B, bm, bn, tid);
        CP_COMMIT();
    }

    for (int t = 0; t < NCH; ++t) {
        if (t + 2 < NCH) CP_WAIT1(); else CP_WAIT0();
        __syncthreads();
        if (t + 2 < NCH) {
            stage_load(sb, (t + 2) % NSTG, t + 2, A, B, bm, bn, tid);
            CP_COMMIT();
        }
        const uint32_t st = sb + (t % NSTG) * STAGE;
        const uint32_t pA = st;
        const uint32_t pB = st + A_BYTES;

        uint32_t a[2][4], b[4][4];
#pragma unroll
        for (int kk = 0; kk < 4; ++kk) {
#pragma unroll
            for (int mt = 0; mt < 2; ++mt)
                ldsm4(a[mt], pA + swz((uint32_t)((wm + mt * 16 + a_r) * 128 + kk * 32 + a_k)));
#pragma unroll
            for (int g = 0; g < 4; ++g)
                ldsm4(b[g], pB + swz((uint32_t)((wn + g * 16 + b_r) * 128 + kk * 32 + b_k)));
#pragma unroll
            for (int mt = 0; mt < 2; ++mt)
#pragma unroll
                for (int g = 0; g < 4; ++g) {
                    mma16816(acc[mt][2 * g],     a[mt], &b[g][0]);
                    mma16816(acc[mt][2 * g + 1], a[mt], &b[g][2]);
                }
        }
        __syncthreads();
    }

    // ------------------------------ epilogue ---------------------------------
    const int erow = (lid >> 2);
    const int ecol = (lid & 3) * 2;

    if (MODE == 1) {
#pragma unroll
        for (int mt = 0; mt < 2; ++mt) {
#pragma unroll
            for (int nt = 0; nt < 8; ++nt) {
                const int col = bn + wn + nt * 8 + ecol;
                const int r0  = bm + wm + mt * 16 + erow;
                float2 v0 = make_float2(acc[mt][nt][0] * INV_YS, acc[mt][nt][1] * INV_YS);
                float2 v1 = make_float2(acc[mt][nt][2] * INV_YS, acc[mt][nt][3] * INV_YS);
                *(float2*)(out0 + (size_t)r0 * D_ + col)       = v0;
                *(float2*)(out0 + (size_t)(r0 + 8) * D_ + col) = v1;
            }
        }
    } else {
        float bnd[15];
#pragma unroll
        for (int b0 = 0; b0 < 15; ++b0) bnd[b0] = s_bound[b0];
#pragma unroll
        for (int mt = 0; mt < 2; ++mt) {
#pragma unroll
            for (int nt = 0; nt < 8; ++nt) {
                const int col = bn + wn + nt * 8 + ecol;
#pragma unroll
                for (int half = 0; half < 2; ++half) {
                    const int r0 = bm + wm + mt * 16 + erow + half * 8;
                    float v0 = acc[mt][nt][half * 2 + 0];  // scaled y' = 2^20 y
                    float v1 = acc[mt][nt][half * 2 + 1];
                    int q0 = 0, q1 = 0;
#pragma unroll
                    for (int b0 = 0; b0 < 15; ++b0) {
                        q0 += (v0 > bnd[b0]) ? 1 : 0;
                        q1 += (v1 > bnd[b0]) ? 1 : 0;
                    }
                    float dl0 = (q0 > 0)  ? v0 - s_bound[q0 - 1] : 1e30f;
                    float dr0 = (q0 < 15) ? s_bound[q0] - v0     : 1e30f;
                    float dl1 = (q1 > 0)  ? v1 - s_bound[q1 - 1] : 1e30f;
                    float dr1 = (q1 < 15) ? s_bound[q1] - v1     : 1e30f;
                    if (fminf(dl0, dr0) < THR) {
                        uint32_t slot = atomicAdd(&g_rowcnt[r0], 1u);
                        if (slot < SLOTS)
                            g_rowflag[(size_t)r0 * SLOTS + slot] =
                                ((uint32_t)col << 4) | (uint32_t)q0;
                    }
                    if (fminf(dl1, dr1) < THR) {
                        uint32_t slot = atomicAdd(&g_rowcnt[r0], 1u);
                        if (slot < SLOTS)
                            g_rowflag[(size_t)r0 * SLOTS + slot] =
                                ((uint32_t)(col + 1) << 4) | (uint32_t)q1;
                    }
                    const size_t off = (size_t)r0 * D_ + col;
                    *(uint32_t*)(g_yhhi + off) =
                        (uint32_t)s_chi[q0] | ((uint32_t)s_chi[q1] << 16);
                    if (write_idx) {
                        float2 f = make_float2((float)q0, (float)q1);
                        *(float2*)(out0 + off) = f;
                    }
                }
            }
        }
    }
}

// ---------------------------- repair kernel -----------------------------------
// One 256-thread CTA per row r: x[r,:] cached in smem; for each flagged
// (c, q_old), exact fp32 warp dot vs Pi[c,:] (L2-resident), unroll 8 for
// MLP=16 (repair is latency-bound: L2 51%, issue 24% at unroll 4).
__global__ __launch_bounds__(256)
void k_repair(const float* __restrict__ x, const float* __restrict__ Pi,
              const float* __restrict__ cent, float* __restrict__ idxf,
              int write_idx)
{
    __shared__ float xs[D_];
    const int r   = blockIdx.x;
    const int tid = threadIdx.x;
    const int wid = tid >> 5, lid = tid & 31;

    uint32_t cnt = g_rowcnt[r];
    if (cnt > SLOTS) cnt = SLOTS;
    if (cnt == 0) return;

    const float* xr = x + (size_t)r * D_;
#pragma unroll
    for (int i = 0; i < D_ / (256 * 4); ++i) {
        int k = (tid + i * 256) * 4;
        *(float4*)(xs + k) = *(const float4*)(xr + k);
    }
    __syncthreads();

    float c16[16], bnd[15];
#pragma unroll
    for (int i = 0; i < 16; ++i) c16[i] = __ldg(cent + i);
#pragma unroll
    for (int i = 0; i < 15; ++i) bnd[i] = 0.5f * (c16[i] + c16[i + 1]);

    for (uint32_t e = (uint32_t)wid; e < cnt; e += 8) {
        uint32_t item = g_rowflag[(size_t)r * SLOTS + e];
        int c    = (int)(item >> 4);
        int qold = (int)(item & 15u);
        const float* pr = Pi + (size_t)c * D_;
        float s0 = 0.f, s1 = 0.f, s2 = 0.f, s3 = 0.f;
#pragma unroll 8
        for (int k = lid * 4; k < D_; k += 128) {
            float4 a = *(const float4*)(xs + k);
            float4 b = *(const float4*)(pr + k);
            s0 = fmaf(a.x, b.x, s0); s1 = fmaf(a.y, b.y, s1);
            s2 = fmaf(a.z, b.z, s2); s3 = fmaf(a.w, b.w, s3);
        }
        float v = (s0 + s1) + (s2 + s3);
#pragma unroll
        for (int o = 16; o; o >>= 1) v += __shfl_xor_sync(0xFFFFFFFFu, v, o);
        if (lid == 0) {
            int q = 0;
#pragma unroll
            for (int b0 = 0; b0 < 15; ++b0) q += (v > bnd[b0]) ? 1 : 0;
            if (q != qold) {
                const size_t off = (size_t)r * D_ + c;
                g_yhhi[off] = __float2half_rn(c16[q] * SCALE);
                if (write_idx) idxf[off] = (float)q;
            }
        }
    }
}

// ---------------------------- prep kernels -----------------------------------
__global__ __launch_bounds__(256)
void k_cvt(const float* __restrict__ src, __half* __restrict__ hi)
{
    const uint32_t gtid = blockIdx.x * 256 + threadIdx.x;
    if (gtid < N_) g_rowcnt[gtid] = 0;
    const size_t i = (size_t)gtid * 4;
    float4 v = *(const float4*)(src + i);
    uint2 uh;
    uh.x = pack2(__float2half_rn(v.x * SCALE), __float2half_rn(v.y * SCALE));
    uh.y = pack2(__float2half_rn(v.z * SCALE), __float2half_rn(v.w * SCALE));
    *(uint2*)(hi + i) = uh;
}

// fused Pi prep: one read of Pi -> g_phi (row-major) + g_pthi (transposed)
__global__ __launch_bounds__(256)
void k_pi(const float* __restrict__ Pi)
{
    __shared__ __half tile[32][33];
    const int bx = blockIdx.x * 32, by = blockIdx.y * 32;
    const int tx = threadIdx.x & 31, ty = threadIdx.x >> 5;
#pragma unroll
    for (int r = 0; r < 4; ++r) {
        const int row = by + ty + r * 8;
        float v = Pi[(size_t)row * D_ + bx + tx] * SCALE;
        __half h = __float2half_rn(v);
        tile[ty + r * 8][tx] = h;
        g_phi[(size_t)row * D_ + bx + tx] = h;
    }
    __syncthreads();
#pragma unroll
    for (int r = 0; r < 4; ++r)
        g_pthi[(size_t)(bx + ty + r * 8) * D_ + by + tx] = tile[tx][ty + r * 8];
}

// ---------------------------- launch ------------------------------------------
extern "C" void kernel_launch(void* const* d_in, const int* in_sizes, int n_in,
                              void* d_out, int out_size)
{
    const float* x    = (const float*)d_in[0];
    const float* Pi   = (const float*)d_in[1];
    const float* cent = (const float*)d_in[2];

    float* out  = (float*)d_out;
    float* xhat = out;
    float* idxf = out + (size_t)N_ * D_;

    const long long total = (long long)N_ * D_;
    const int write_idx = ((long long)out_size >= 2 * total) ? 1 : 0;

    cudaFuncSetAttribute(tq_mma<0>, cudaFuncAttributeMaxDynamicSharedMemorySize, SMEM_SZ);
    cudaFuncSetAttribute(tq_mma<1>, cudaFuncAttributeMaxDynamicSharedMemorySize, SMEM_SZ);

    __half* xhi_p;
    cudaGetSymbolAddress((void**)&xhi_p, g_xhi);

    const int nblk = (int)(total / (4 * 256));                 // 16384
    k_cvt<<<nblk, 256>>>(x, xhi_p);
    k_pi<<<dim3(D_ / 32, D_ / 32), 256>>>(Pi);

    dim3 grid(D_ / BN, N_ / BM);   // (32, 32) = 1024 CTAs, 2 per SM
    tq_mma<0><<<grid, NTH, SMEM_SZ>>>(cent, idxf, write_idx);
    k_repair<<<N_, 256>>>(x, Pi, cent, idxf, write_idx);
    tq_mma<1><<<grid, NTH, SMEM_SZ>>>(nullptr, xhat, 0);
}

// round 17
// speedup vs baseline: 1.3696x; 1.0205x over previous
#include <cuda_runtime.h>
#include <cuda_fp16.h>
#include <cstdint>
#include <cstddef>

// ============================================================================
// TurboQuantMSE via mma.sync fp16 (HMMA, sm_80 ISA — valid on plain sm_103).
// Both GEMMs are SINGLE-product fp16 (operands scaled by 2^10).
// 128x128 tiles, 256 threads, 2 CTAs/SM (launch_bounds(256,2), 3-stage 96KB
// pipeline) — 16 warps/SM with smoothed wave tails (round-15 winner).
// GEMM1 flags boundary-adjacent values (THR=14 scaled units, 3.2 sigma of
// calibrated residual sigma=4.35) into PER-ROW buckets; repair (one
// 256-thread CTA per row, x row in smem, Pi from L2, unroll-16 dot for
// maximum MLP — repair is L2-latency-bound) patches idx + yhat before GEMM2.
// ============================================================================

#define DEVFN __device__ __forceinline__

namespace {
constexpr int N_  = 4096;
constexpr int D_  = 4096;
constexpr int BM  = 128;
constexpr int BN  = 128;
constexpr int BKE = 64;                 // K elements per chunk (fp16)
constexpr int NCH = D_ / BKE;           // 64 chunks
constexpr int NTH = 256;                // 8 warps, 2 CTAs/SM

constexpr float SCALE   = 1024.0f;             // 2^10, exact
constexpr float YSCALE  = 1048576.0f;          // 2^20, exact
constexpr float INV_YS  = 1.0f / 1048576.0f;   // exact power of two
constexpr float THR     = 14.0f;               // flag threshold (scaled units)

constexpr int A_BYTES = BM * 128;       // 16 KB
constexpr int B_BYTES = BN * 128;       // 16 KB
constexpr int STAGE   = A_BYTES + B_BYTES;     // 32 KB
constexpr int NSTG    = 3;
constexpr int SMEM_SZ = NSTG * STAGE;          // 96 KB

constexpr int SLOTS = 96;               // flag slots per row (mean ~16)
}

// -------- device scratch (allocation-free rule: device globals) -------------
__device__ __half    g_xhi [(size_t)N_ * D_];
__device__ __half    g_phi [(size_t)D_ * D_];
__device__ __half    g_pthi[(size_t)D_ * D_];
__device__ __half    g_yhhi[(size_t)N_ * D_];
__device__ uint32_t  g_rowcnt[N_];
__device__ uint32_t  g_rowflag[(size_t)N_ * SLOTS];   // (c<<4)|q

// ---------------------------- PTX helpers -----------------------------------
DEVFN uint32_t smem_u32(const void* p) {
    uint32_t a;
    asm("{ .reg .u64 t; cvta.to.shared.u64 t, %1; cvt.u32.u64 %0, t; }" : "=r"(a) : "l"(p));
    return a;
}
DEVFN void cpasync16(uint32_t s, const void* g) {
    asm volatile("cp.async.cg.shared.global [%0], [%1], 16;" :: "r"(s), "l"(g));
}
#define CP_COMMIT() asm volatile("cp.async.commit_group;" ::: "memory")
#define CP_WAIT1()  asm volatile("cp.async.wait_group 1;" ::: "memory")
#define CP_WAIT0()  asm volatile("cp.async.wait_group 0;" ::: "memory")

DEVFN void ldsm4(uint32_t* r, uint32_t addr) {
    asm volatile("ldmatrix.sync.aligned.m8n8.x4.shared.b16 {%0,%1,%2,%3}, [%4];"
                 : "=r"(r[0]), "=r"(r[1]), "=r"(r[2]), "=r"(r[3]) : "r"(addr));
}
DEVFN void mma16816(float* c, const uint32_t* a, const uint32_t* b) {
    asm volatile(
        "mma.sync.aligned.m16n8k16.row.col.f32.f16.f16.f32 "
        "{%0,%1,%2,%3}, {%4,%5,%6,%7}, {%8,%9}, {%0,%1,%2,%3};"
        : "+f"(c[0]), "+f"(c[1]), "+f"(c[2]), "+f"(c[3])
        : "r"(a[0]), "r"(a[1]), "r"(a[2]), "r"(a[3]), "r"(b[0]), "r"(b[1]));
}
DEVFN uint32_t pack2(__half a, __half b) {
    return (uint32_t)__half_as_ushort(a) | ((uint32_t)__half_as_ushort(b) << 16);
}
DEVFN uint32_t swz(uint32_t off) { return off ^ ((off >> 3) & 0x70); }

// ---------------------------- staging loader ---------------------------------
template<int ROWS>
DEVFN void ld_op(uint32_t sdst, const __half* __restrict__ g,
                 int row0, int kc, int tid)
{
    const char* gb = (const char*)g + ((size_t)row0 * D_ + (size_t)kc * BKE) * 2;
    constexpr int NOPS = ROWS * 8;             // 16B ops
#pragma unroll
    for (int i = 0; i < NOPS / NTH; ++i) {
        int idx = tid + i * NTH;
        int r = idx >> 3;
        int c = (idx & 7) << 4;
        cpasync16(sdst + swz((uint32_t)(r * 128 + c)),
                  gb + (size_t)r * (D_ * 2) + c);
    }
}

DEVFN void stage_load(uint32_t sb, int s, int kc,
                      const __half* A, const __half* B, int bm, int bn, int tid)
{
    const uint32_t st = sb + s * STAGE;
    ld_op<BM>(st,           A, bm, kc, tid);
    ld_op<BN>(st + A_BYTES, B, bn, kc, tid);
}

// ---------------------------- main GEMM kernel -------------------------------
// MODE 0: GEMM1 (x_hi, Pi_hi)     -> quantize epilogue, flag into row buckets
// MODE 1: GEMM2 (yhat_hi, PiT_hi) -> fp32 store * 2^-20
template<int MODE>
__global__ __launch_bounds__(NTH, 2)
void tq_mma(const float* __restrict__ cent, float* __restrict__ out0, int write_idx)
{
    extern __shared__ char smem[];
    const uint32_t sb = smem_u32(smem);
    const int tid = threadIdx.x, wid = tid >> 5, lid = tid & 31;
    const int bm = blockIdx.y * BM;
    const int bn = blockIdx.x * BN;

    const __half* A = (MODE == 0) ? g_xhi : g_yhhi;
    const __half* B = (MODE == 0) ? g_phi : g_pthi;

    __shared__ float    s_bound[16];
    __shared__ uint16_t s_chi[16];
    if (MODE == 0) {
        if (tid < 16) {
            float cs = cent[tid] * SCALE;           // exact
            s_chi[tid] = __half_as_ushort(__float2half_rn(cs));
        }
        if (tid < 15) s_bound[tid] = (0.5f * (cent[tid] + cent[tid + 1])) * YSCALE;
    }

    // 8 warps: 4 (M) x 2 (N), each 32x64
    const int wm = (wid & 3) * 32;
    const int wn = (wid >> 2) * 64;

    const int a_r = lid & 15;
    const int a_k = (lid >> 4) << 4;
    const int b_r = (lid & 7) | ((lid >> 4) << 3);
    const int b_k = ((lid >> 3) & 1) << 4;

    float acc[2][8][4];
#pragma unroll
    for (int i = 0; i < 2; ++i)
#pragma unroll
        for (int j = 0; j < 8; ++j)
#pragma unroll
            for (int k = 0; k < 4; ++k) acc[i][j][k] = 0.0f;

    // prologue: prime 2 of 3 stages
#pragma unroll
    for (int s = 0; s < 2; ++s) {
        stage_load(sb, s, s, A, B, bm, bn, tid);
        CP_COMMIT();
    }

    for (int t = 0; t < NCH; ++t) {
        if (t + 2 < NCH) CP_WAIT1(); else CP_WAIT0();
        __syncthreads();
        if (t + 2 < NCH) {
            stage_load(sb, (t + 2) % NSTG, t + 2, A, B, bm, bn, tid);
            CP_COMMIT();
        }
        const uint32_t st = sb + (t % NSTG) * STAGE;
        const uint32_t pA = st;
        const uint32_t pB = st + A_BYTES;

        uint32_t a[2][4], b[4][4];
#pragma unroll
        for (int kk = 0; kk < 4; ++kk) {
#pragma unroll
            for (int mt = 0; mt < 2; ++mt)
                ldsm4(a[mt], pA + swz((uint32_t)((wm + mt * 16 + a_r) * 128 + kk * 32 + a_k)));
#pragma unroll
            for (int g = 0; g < 4; ++g)
                ldsm4(b[g], pB + swz((uint32_t)((wn + g * 16 + b_r) * 128 + kk * 32 + b_k)));
#pragma unroll
            for (int mt = 0; mt < 2; ++mt)
#pragma unroll
                for (int g = 0; g < 4; ++g) {
                    mma16816(acc[mt][2 * g],     a[mt], &b[g][0]);
                    mma16816(acc[mt][2 * g + 1], a[mt], &b[g][2]);
                }
        }
        __syncthreads();
    }

    // ------------------------------ epilogue ---------------------------------
    const int erow = (lid >> 2);
    const int ecol = (lid & 3) * 2;

    if (MODE == 1) {
#pragma unroll
        for (int mt = 0; mt < 2; ++mt) {
#pragma unroll
            for (int nt = 0; nt < 8; ++nt) {
                const int col = bn + wn + nt * 8 + ecol;
                const int r0  = bm + wm + mt * 16 + erow;
                float2 v0 = make_float2(acc[mt][nt][0] * INV_YS, acc[mt][nt][1] * INV_YS);
                float2 v1 = make_float2(acc[mt][nt][2] * INV_YS, acc[mt][nt][3] * INV_YS);
                *(float2*)(out0 + (size_t)r0 * D_ + col)       = v0;
                *(float2*)(out0 + (size_t)(r0 + 8) * D_ + col) = v1;
            }
        }
    } else {
        float bnd[15];
#pragma unroll
        for (int b0 = 0; b0 < 15; ++b0) bnd[b0] = s_bound[b0];
#pragma unroll
        for (int mt = 0; mt < 2; ++mt) {
#pragma unroll
            for (int nt = 0; nt < 8; ++nt) {
                const int col = bn + wn + nt * 8 + ecol;
#pragma unroll
                for (int half = 0; half < 2; ++half) {
                    const int r0 = bm + wm + mt * 16 + erow + half * 8;
                    float v0 = acc[mt][nt][half * 2 + 0];  // scaled y' = 2^20 y
                    float v1 = acc[mt][nt][half * 2 + 1];
                    int q0 = 0, q1 = 0;
#pragma unroll
                    for (int b0 = 0; b0 < 15; ++b0) {
                        q0 += (v0 > bnd[b0]) ? 1 : 0;
                        q1 += (v1 > bnd[b0]) ? 1 : 0;
                    }
                    float dl0 = (q0 > 0)  ? v0 - s_bound[q0 - 1] : 1e30f;
                    float dr0 = (q0 < 15) ? s_bound[q0] - v0     : 1e30f;
                    float dl1 = (q1 > 0)  ? v1 - s_bound[q1 - 1] : 1e30f;
                    float dr1 = (q1 < 15) ? s_bound[q1] - v1     : 1e30f;
                    if (fminf(dl0, dr0) < THR) {
                        uint32_t slot = atomicAdd(&g_rowcnt[r0], 1u);
                        if (slot < SLOTS)
                            g_rowflag[(size_t)r0 * SLOTS + slot] =
                                ((uint32_t)col << 4) | (uint32_t)q0;
                    }
                    if (fminf(dl1, dr1) < THR) {
                        uint32_t slot = atomicAdd(&g_rowcnt[r0], 1u);
                        if (slot < SLOTS)
                            g_rowflag[(size_t)r0 * SLOTS + slot] =
                                ((uint32_t)(col + 1) << 4) | (uint32_t)q1;
                    }
                    const size_t off = (size_t)r0 * D_ + col;
                    *(uint32_t*)(g_yhhi + off) =
                        (uint32_t)s_chi[q0] | ((uint32_t)s_chi[q1] << 16);
                    if (write_idx) {
                        float2 f = make_float2((float)q0, (float)q1);
                        *(float2*)(out0 + off) = f;
                    }
                }
            }
        }
    }
}

// ---------------------------- repair kernel -----------------------------------
// One 256-thread CTA per row r: x[r,:] cached in smem; for each flagged
// (c, q_old), exact fp32 warp dot vs Pi[c,:] (L2-resident). unroll 16 to
// maximize in-flight loads (repair is L2-latency-bound: L2 50%, issue 23%).
__global__ __launch_bounds__(256)
void k_repair(const float* __restrict__ x, const float* __restrict__ Pi,
              const float* __restrict__ cent, float* __restrict__ idxf,
              int write_idx)
{
    __shared__ float xs[D_];
    const int r   = blockIdx.x;
    const int tid = threadIdx.x;
    const int wid = tid >> 5, lid = tid & 31;

    uint32_t cnt = g_rowcnt[r];
    if (cnt > SLOTS) cnt = SLOTS;
    if (cnt == 0) return;

    const float* xr = x + (size_t)r * D_;
#pragma unroll
    for (int i = 0; i < D_ / (256 * 4); ++i) {
        int k = (tid + i * 256) * 4;
        *(float4*)(xs + k) = *(const float4*)(xr + k);
    }
    __syncthreads();

    float c16[16], bnd[15];
#pragma unroll
    for (int i = 0; i < 16; ++i) c16[i] = __ldg(cent + i);
#pragma unroll
    for (int i = 0; i < 15; ++i) bnd[i] = 0.5f * (c16[i] + c16[i + 1]);

    for (uint32_t e = (uint32_t)wid; e < cnt; e += 8) {
        uint32_t item = g_rowflag[(size_t)r * SLOTS + e];
        int c    = (int)(item >> 4);
        int qold = (int)(item & 15u);
        const float* pr = Pi + (size_t)c * D_;
        float s0 = 0.f, s1 = 0.f, s2 = 0.f, s3 = 0.f;
#pragma unroll 16
        for (int k = lid * 4; k < D_; k += 128) {
            float4 a = *(const float4*)(xs + k);
            float4 b = *(const float4*)(pr + k);
            s0 = fmaf(a.x, b.x, s0); s1 = fmaf(a.y, b.y, s1);
            s2 = fmaf(a.z, b.z, s2); s3 = fmaf(a.w, b.w, s3);
        }
        float v = (s0 + s1) + (s2 + s3);
#pragma unroll
        for (int o = 16; o; o >>= 1) v += __shfl_xor_sync(0xFFFFFFFFu, v, o);
        if (lid == 0) {
            int q = 0;
#pragma unroll
            for (int b0 = 0; b0 < 15; ++b0) q += (v > bnd[b0]) ? 1 : 0;
            if (q != qold) {
                const size_t off = (size_t)r * D_ + c;
                g_yhhi[off] = __float2half_rn(c16[q] * SCALE);
                if (write_idx) idxf[off] = (float)q;
            }
        }
    }
}

// ---------------------------- prep kernels -----------------------------------
__global__ __launch_bounds__(256)
void k_cvt(const float* __restrict__ src, __half* __restrict__ hi)
{
    const uint32_t gtid = blockIdx.x * 256 + threadIdx.x;
    if (gtid < N_) g_rowcnt[gtid] = 0;
    const size_t i = (size_t)gtid * 4;
    float4 v = *(const float4*)(src + i);
    uint2 uh;
    uh.x = pack2(__float2half_rn(v.x * SCALE), __float2half_rn(v.y * SCALE));
    uh.y = pack2(__float2half_rn(v.z * SCALE), __float2half_rn(v.w * SCALE));
    *(uint2*)(hi + i) = uh;
}

// fused Pi prep: one read of Pi -> g_phi (row-major) + g_pthi (transposed)
__global__ __launch_bounds__(256)
void k_pi(const float* __restrict__ Pi)
{
    __shared__ __half tile[32][33];
    const int bx = blockIdx.x * 32, by = blockIdx.y * 32;
    const int tx = threadIdx.x & 31, ty = threadIdx.x >> 5;
#pragma unroll
    for (int r = 0; r < 4; ++r) {
        const int row = by + ty + r * 8;
        float v = Pi[(size_t)row * D_ + bx + tx] * SCALE;
        __half h = __float2half_rn(v);
        tile[ty + r * 8][tx] = h;
        g_phi[(size_t)row * D_ + bx + tx] = h;
    }
    __syncthreads();
#pragma unroll
    for (int r = 0; r < 4; ++r)
        g_pthi[(size_t)(bx + ty + r * 8) * D_ + by + tx] = tile[tx][ty + r * 8];
}

// ---------------------------- launch ------------------------------------------
extern "C" void kernel_launch(void* const* d_in, const int* in_sizes, int n_in,
                              void* d_out, int out_size)
{
    const float* x    = (const float*)d_in[0];
    const float* Pi   = (const float*)d_in[1];
    const float* cent = (const float*)d_in[2];

    float* out  = (float*)d_out;
    float* xhat = out;
    float* idxf = out + (size_t)N_ * D_;

    const long long total = (long long)N_ * D_;
    const int write_idx = ((long long)out_size >= 2 * total) ? 1 : 0;

    cudaFuncSetAttribute(tq_mma<0>, cudaFuncAttributeMaxDynamicSharedMemorySize, SMEM_SZ);
    cudaFuncSetAttribute(tq_mma<1>, cudaFuncAttributeMaxDynamicSharedMemorySize, SMEM_SZ);

    __half* xhi_p;
    cudaGetSymbolAddress((void**)&xhi_p, g_xhi);

    const int nblk = (int)(total / (4 * 256));                 // 16384
    k_cvt<<<nblk, 256>>>(x, xhi_p);
    k_pi<<<dim3(D_ / 32, D_ / 32), 256>>>(Pi);

    dim3 grid(D_ / BN, N_ / BM);   // (32, 32) = 1024 CTAs, 2 per SM
    tq_mma<0><<<grid, NTH, SMEM_SZ>>>(cent, idxf, write_idx);
    k_repair<<<N_, 256>>>(x, Pi, cent, idxf, write_idx);
    tq_mma<1><<<grid, NTH, SMEM_SZ>>>(nullptr, xhat, 0);
}